// round 8
// baseline (speedup 1.0000x reference)
#include <cuda_runtime.h>
#include <cuda_bf16.h>
#include <math_constants.h>

// Problem constants
#define BATCH 2
#define SEQ   2048
#define DMODEL 1024
#define NHEAD 16
#define HDIM  64
#define MROWS (BATCH*SEQ)   // 4096

// ---------------- scratch (device globals: allowed) ----------------
__device__ float g_q[BATCH*SEQ*DMODEL];
__device__ float g_k[BATCH*SEQ*DMODEL];
__device__ float g_v[BATCH*SEQ*DMODEL];
__device__ float g_pooled[BATCH*DMODEL];
__device__ float g_gate[BATCH*NHEAD];

// ---------------- fused QKV GEMM: C_z[M,N] = A[M,K] @ W_z[K,N] + b_z ----------
// blockIdx.z in {0,1,2} selects (Wq->g_q, Wk->g_k, Wv->g_v).
// 128x128 block tile, BK=8, 256 threads, 8x8 microtile.
__global__ __launch_bounds__(256, 2)
void qkv_gemm(const float* __restrict__ A,
              const float* __restrict__ Wq, const float* __restrict__ bq,
              const float* __restrict__ Wk, const float* __restrict__ bk,
              const float* __restrict__ Wv, const float* __restrict__ bv) {
    const float* W;
    const float* bias;
    float* C;
    if (blockIdx.z == 0)      { W = Wq; bias = bq; C = g_q; }
    else if (blockIdx.z == 1) { W = Wk; bias = bk; C = g_k; }
    else                      { W = Wv; bias = bv; C = g_v; }

    __shared__ float As[8 * 128];   // transposed: As[k][m]
    __shared__ float Bs[8 * 128];   // Bs[k][n]
    const int tid = threadIdx.x;
    const int tx = tid & 15;        // 0..15 -> n microtile
    const int ty = tid >> 4;        // 0..15 -> m microtile
    const int row0 = blockIdx.y * 128;
    const int col0 = blockIdx.x * 128;

    float acc[8][8];
#pragma unroll
    for (int i = 0; i < 8; i++)
#pragma unroll
        for (int j = 0; j < 8; j++) acc[i][j] = 0.f;

    for (int k0 = 0; k0 < DMODEL; k0 += 8) {
        // load A tile 128x8 -> transposed into As
        {
            const int r = tid >> 1;
            const int c = (tid & 1) * 4;
            const float4 av = *(const float4*)&A[(size_t)(row0 + r) * DMODEL + k0 + c];
            As[(c + 0) * 128 + r] = av.x;
            As[(c + 1) * 128 + r] = av.y;
            As[(c + 2) * 128 + r] = av.z;
            As[(c + 3) * 128 + r] = av.w;
        }
        // load W tile 8x128
        {
            const int r = tid >> 5;
            const int c = (tid & 31) * 4;
            *(float4*)&Bs[r * 128 + c] =
                *(const float4*)&W[(size_t)(k0 + r) * DMODEL + col0 + c];
        }
        __syncthreads();
#pragma unroll
        for (int kk = 0; kk < 8; kk++) {
            float a[8], b[8];
            *(float4*)&a[0] = *(float4*)&As[kk * 128 + ty * 8];
            *(float4*)&a[4] = *(float4*)&As[kk * 128 + ty * 8 + 4];
            *(float4*)&b[0] = *(float4*)&Bs[kk * 128 + tx * 8];
            *(float4*)&b[4] = *(float4*)&Bs[kk * 128 + tx * 8 + 4];
#pragma unroll
            for (int i = 0; i < 8; i++)
#pragma unroll
                for (int j = 0; j < 8; j++) acc[i][j] += a[i] * b[j];
        }
        __syncthreads();
    }

#pragma unroll
    for (int i = 0; i < 8; i++) {
        const int r = row0 + ty * 8 + i;
#pragma unroll
        for (int j4 = 0; j4 < 2; j4++) {
            const int c = col0 + tx * 8 + j4 * 4;
            float4 o;
            o.x = acc[i][j4 * 4 + 0] + bias[c + 0];
            o.y = acc[i][j4 * 4 + 1] + bias[c + 1];
            o.z = acc[i][j4 * 4 + 2] + bias[c + 2];
            o.w = acc[i][j4 * 4 + 3] + bias[c + 3];
            *(float4*)&C[(size_t)r * DMODEL + c] = o;
        }
    }
}

// ---------------- mean pool over sequence ----------------
__global__ void pool_kernel(const float* __restrict__ X) {
    const int gid = blockIdx.x * blockDim.x + threadIdx.x;  // 0..2047
    if (gid >= BATCH * DMODEL) return;
    const int b = gid >> 10;
    const int d = gid & 1023;
    const float* p = X + (size_t)b * SEQ * DMODEL + d;
    float s = 0.f;
    for (int i = 0; i < SEQ; i++) s += p[(size_t)i * DMODEL];
    g_pooled[gid] = s * (1.0f / (float)SEQ);
}

// ---------------- head-gate predictor ----------------
__global__ void gate_kernel(const float* __restrict__ pW1, const float* __restrict__ pb1,
                            const float* __restrict__ gamma, const float* __restrict__ beta,
                            const float* __restrict__ mean, const float* __restrict__ var,
                            const float* __restrict__ pW2, const float* __restrict__ pb2) {
    __shared__ float hsm[BATCH][64];
    const int t = threadIdx.x;
    if (t < BATCH * 64) {
        const int b = t >> 6;
        const int j = t & 63;
        float acc = pb1[j];
        for (int d = 0; d < DMODEL; d++) acc += g_pooled[b * DMODEL + d] * pW1[d * 64 + j];
        acc = (acc - mean[j]) * (1.0f / sqrtf(var[j] + 1e-12f)) * gamma[j] + beta[j];
        hsm[b][j] = fmaxf(acc, 0.f);
    }
    __syncthreads();
    if (t < BATCH * NHEAD) {
        const int b = t >> 4;
        const int o = t & 15;
        float acc = pb2[o];
        for (int j = 0; j < 64; j++) acc += hsm[b][j] * pW2[j * NHEAD + o];
        g_gate[b * NHEAD + o] = (acc >= 0.f) ? 1.f : 0.f;
    }
}

// ---------------- flash attention (fp32), 64 q-rows per block ----------------
// thread layout: 256 threads, tx = tid&15 (k-col / out-dim microtile of 4),
//                            ty = tid>>4 (q-row microtile of 4)
#define APAD 68   // row stride in floats (pad: bank-safe, float4-aligned)
#define ASMEM_FLOATS (4 * 64 * APAD + 64)

__global__ __launch_bounds__(256)
void attn_kernel(const float* __restrict__ mask, float* __restrict__ out) {
    extern __shared__ float sm[];
    float* Qs = sm;                    // 64 x APAD
    float* Ks = Qs + 64 * APAD;
    float* Vs = Ks + 64 * APAD;
    float* Ps = Vs + 64 * APAD;
    float* Ms = Ps + 64 * APAD;        // 64 mask values

    const int bh = blockIdx.x;
    const int b = bh >> 4;
    const int h = bh & 15;
    const int q0 = blockIdx.y * 64;
    const int tid = threadIdx.x;
    const int tx = tid & 15;
    const int ty = tid >> 4;
    const int qr = ty * 4;
    const int kc = tx * 4;
    const float scale = 0.125f;  // 1/sqrt(64)
    const float gate = g_gate[b * NHEAD + h];

    // load Q tile: rows q0..q0+63 of head h
    {
        const float* qg = g_q + ((size_t)(b * SEQ + q0)) * DMODEL + h * HDIM;
        for (int i = tid; i < 64 * 16; i += 256) {
            const int r = i >> 4;
            const int c4 = (i & 15) * 4;
            *(float4*)&Qs[r * APAD + c4] = *(const float4*)&qg[(size_t)r * DMODEL + c4];
        }
    }

    float m[4], l[4];
    float4 acc[4];
#pragma unroll
    for (int i = 0; i < 4; i++) {
        m[i] = -CUDART_INF_F;
        l[i] = 0.f;
        acc[i] = make_float4(0.f, 0.f, 0.f, 0.f);
    }

    for (int kt = 0; kt < SEQ / 64; kt++) {
        __syncthreads();  // guard prior-iter reads of Ks/Vs/Ps
        {
            const float* kg = g_k + ((size_t)(b * SEQ + kt * 64)) * DMODEL + h * HDIM;
            const float* vg = g_v + ((size_t)(b * SEQ + kt * 64)) * DMODEL + h * HDIM;
            for (int i = tid; i < 64 * 16; i += 256) {
                const int r = i >> 4;
                const int c4 = (i & 15) * 4;
                *(float4*)&Ks[r * APAD + c4] = *(const float4*)&kg[(size_t)r * DMODEL + c4];
                *(float4*)&Vs[r * APAD + c4] = *(const float4*)&vg[(size_t)r * DMODEL + c4];
            }
            if (tid < 64) Ms[tid] = mask[b * SEQ + kt * 64 + tid];
        }
        __syncthreads();

        // scores microtile s[4][4] = Q[qr..][*] . K[kc..][*]
        float s[4][4];
#pragma unroll
        for (int i = 0; i < 4; i++)
#pragma unroll
            for (int j = 0; j < 4; j++) s[i][j] = 0.f;

#pragma unroll
        for (int d4 = 0; d4 < 16; d4++) {
            float4 qv[4], kv[4];
#pragma unroll
            for (int i = 0; i < 4; i++) qv[i] = *(float4*)&Qs[(qr + i) * APAD + d4 * 4];
#pragma unroll
            for (int j = 0; j < 4; j++) kv[j] = *(float4*)&Ks[(kc + j) * APAD + d4 * 4];
#pragma unroll
            for (int i = 0; i < 4; i++)
#pragma unroll
                for (int j = 0; j < 4; j++)
                    s[i][j] += qv[i].x * kv[j].x + qv[i].y * kv[j].y +
                               qv[i].z * kv[j].z + qv[i].w * kv[j].w;
        }

        // online softmax per q-row (rows split over 16 lanes sharing same ty)
#pragma unroll
        for (int i = 0; i < 4; i++) {
            float mx = -CUDART_INF_F;
#pragma unroll
            for (int j = 0; j < 4; j++) {
                s[i][j] = s[i][j] * scale + Ms[kc + j];
                mx = fmaxf(mx, s[i][j]);
            }
#pragma unroll
            for (int o = 8; o >= 1; o >>= 1)
                mx = fmaxf(mx, __shfl_xor_sync(0xffffffffu, mx, o));
            const float mn = fmaxf(m[i], mx);
            const float corr = __expf(m[i] - mn);
            float ps = 0.f;
#pragma unroll
            for (int j = 0; j < 4; j++) {
                const float e = __expf(s[i][j] - mn);
                s[i][j] = e;
                ps += e;
            }
#pragma unroll
            for (int o = 8; o >= 1; o >>= 1)
                ps += __shfl_xor_sync(0xffffffffu, ps, o);
            l[i] = l[i] * corr + ps;
            m[i] = mn;
            acc[i].x *= corr; acc[i].y *= corr; acc[i].z *= corr; acc[i].w *= corr;
            *(float4*)&Ps[(qr + i) * APAD + kc] = make_float4(s[i][0], s[i][1], s[i][2], s[i][3]);
        }
        __syncthreads();

        // PV: acc[i][0..3] over out-dims kc..kc+3
#pragma unroll 4
        for (int k = 0; k < 64; k++) {
            const float4 vv = *(float4*)&Vs[k * APAD + kc];
#pragma unroll
            for (int i = 0; i < 4; i++) {
                const float p = Ps[(qr + i) * APAD + k];
                acc[i].x += p * vv.x;
                acc[i].y += p * vv.y;
                acc[i].z += p * vv.z;
                acc[i].w += p * vv.w;
            }
        }
    }

    // epilogue: normalize + gate, write [b, q, h*64 + d]
    float* og = out + ((size_t)(b * SEQ + q0)) * DMODEL + h * HDIM;
#pragma unroll
    for (int i = 0; i < 4; i++) {
        const float inv = gate / l[i];
        float4 o4 = acc[i];
        o4.x *= inv; o4.y *= inv; o4.z *= inv; o4.w *= inv;
        *(float4*)&og[(size_t)(qr + i) * DMODEL + kc] = o4;
    }
}

// ---------------- launch ----------------
extern "C" void kernel_launch(void* const* d_in, const int* in_sizes, int n_in,
                              void* d_out, int out_size) {
    const float* X     = (const float*)d_in[0];
    const float* mask  = (const float*)d_in[1];
    const float* Wq    = (const float*)d_in[2];
    const float* bq    = (const float*)d_in[3];
    const float* Wk    = (const float*)d_in[4];
    const float* bk    = (const float*)d_in[5];
    const float* Wv    = (const float*)d_in[6];
    const float* bv    = (const float*)d_in[7];
    const float* pW1   = (const float*)d_in[8];
    const float* pb1   = (const float*)d_in[9];
    const float* gamma = (const float*)d_in[10];
    const float* beta  = (const float*)d_in[11];
    const float* mean  = (const float*)d_in[12];
    const float* var   = (const float*)d_in[13];
    const float* pW2   = (const float*)d_in[14];
    const float* pb2   = (const float*)d_in[15];
    float* out = (float*)d_out;

    dim3 gg(DMODEL / 128, MROWS / 128, 3);
    qkv_gemm<<<gg, 256>>>(X, Wq, bq, Wk, bk, Wv, bv);

    pool_kernel<<<(BATCH * DMODEL + 255) / 256, 256>>>(X);
    gate_kernel<<<1, 128>>>(pW1, pb1, gamma, beta, mean, var, pW2, pb2);

    const int smem = ASMEM_FLOATS * (int)sizeof(float);
    cudaFuncSetAttribute(attn_kernel, cudaFuncAttributeMaxDynamicSharedMemorySize, smem);
    attn_kernel<<<dim3(BATCH * NHEAD, SEQ / 64), 256, smem>>>(mask, out);
}

// round 10
// speedup vs baseline: 1.4591x; 1.4591x over previous
#include <cuda_runtime.h>
#include <cuda_bf16.h>
#include <math_constants.h>

// Problem constants
#define BATCH 2
#define SEQ   2048
#define DMODEL 1024
#define NHEAD 16
#define HDIM  64
#define MROWS (BATCH*SEQ)   // 4096

// ---------------- scratch (device globals: allowed) ----------------
__device__ float g_q[BATCH*SEQ*DMODEL];
__device__ float g_k[BATCH*SEQ*DMODEL];
__device__ float g_v[BATCH*SEQ*DMODEL];
__device__ float g_pooled[BATCH*DMODEL];
__device__ float g_gate[BATCH*NHEAD];

// ---------------- fused QKV GEMM: C_z[M,N] = A[M,K] @ W_z[K,N] + b_z ----------
__global__ __launch_bounds__(256, 2)
void qkv_gemm(const float* __restrict__ A,
              const float* __restrict__ Wq, const float* __restrict__ bq,
              const float* __restrict__ Wk, const float* __restrict__ bk,
              const float* __restrict__ Wv, const float* __restrict__ bv) {
    const float* W;
    const float* bias;
    float* C;
    if (blockIdx.z == 0)      { W = Wq; bias = bq; C = g_q; }
    else if (blockIdx.z == 1) { W = Wk; bias = bk; C = g_k; }
    else                      { W = Wv; bias = bv; C = g_v; }

    __shared__ float As[8 * 128];   // transposed: As[k][m]
    __shared__ float Bs[8 * 128];   // Bs[k][n]
    const int tid = threadIdx.x;
    const int tx = tid & 15;
    const int ty = tid >> 4;
    const int row0 = blockIdx.y * 128;
    const int col0 = blockIdx.x * 128;

    float acc[8][8];
#pragma unroll
    for (int i = 0; i < 8; i++)
#pragma unroll
        for (int j = 0; j < 8; j++) acc[i][j] = 0.f;

    for (int k0 = 0; k0 < DMODEL; k0 += 8) {
        {
            const int r = tid >> 1;
            const int c = (tid & 1) * 4;
            const float4 av = *(const float4*)&A[(size_t)(row0 + r) * DMODEL + k0 + c];
            As[(c + 0) * 128 + r] = av.x;
            As[(c + 1) * 128 + r] = av.y;
            As[(c + 2) * 128 + r] = av.z;
            As[(c + 3) * 128 + r] = av.w;
        }
        {
            const int r = tid >> 5;
            const int c = (tid & 31) * 4;
            *(float4*)&Bs[r * 128 + c] =
                *(const float4*)&W[(size_t)(k0 + r) * DMODEL + col0 + c];
        }
        __syncthreads();
#pragma unroll
        for (int kk = 0; kk < 8; kk++) {
            float a[8], b[8];
            *(float4*)&a[0] = *(float4*)&As[kk * 128 + ty * 8];
            *(float4*)&a[4] = *(float4*)&As[kk * 128 + ty * 8 + 4];
            *(float4*)&b[0] = *(float4*)&Bs[kk * 128 + tx * 8];
            *(float4*)&b[4] = *(float4*)&Bs[kk * 128 + tx * 8 + 4];
#pragma unroll
            for (int i = 0; i < 8; i++)
#pragma unroll
                for (int j = 0; j < 8; j++) acc[i][j] += a[i] * b[j];
        }
        __syncthreads();
    }

#pragma unroll
    for (int i = 0; i < 8; i++) {
        const int r = row0 + ty * 8 + i;
#pragma unroll
        for (int j4 = 0; j4 < 2; j4++) {
            const int c = col0 + tx * 8 + j4 * 4;
            float4 o;
            o.x = acc[i][j4 * 4 + 0] + bias[c + 0];
            o.y = acc[i][j4 * 4 + 1] + bias[c + 1];
            o.z = acc[i][j4 * 4 + 2] + bias[c + 2];
            o.w = acc[i][j4 * 4 + 3] + bias[c + 3];
            *(float4*)&C[(size_t)r * DMODEL + c] = o;
        }
    }
}

// ---------------- mean pool over sequence ----------------
__global__ void pool_kernel(const float* __restrict__ X) {
    const int gid = blockIdx.x * blockDim.x + threadIdx.x;
    if (gid >= BATCH * DMODEL) return;
    const int b = gid >> 10;
    const int d = gid & 1023;
    const float* p = X + (size_t)b * SEQ * DMODEL + d;
    float s = 0.f;
    for (int i = 0; i < SEQ; i++) s += p[(size_t)i * DMODEL];
    g_pooled[gid] = s * (1.0f / (float)SEQ);
}

// ---------------- head-gate predictor ----------------
__global__ void gate_kernel(const float* __restrict__ pW1, const float* __restrict__ pb1,
                            const float* __restrict__ gamma, const float* __restrict__ beta,
                            const float* __restrict__ mean, const float* __restrict__ var,
                            const float* __restrict__ pW2, const float* __restrict__ pb2) {
    __shared__ float hsm[BATCH][64];
    const int t = threadIdx.x;
    if (t < BATCH * 64) {
        const int b = t >> 6;
        const int j = t & 63;
        float acc = pb1[j];
        for (int d = 0; d < DMODEL; d++) acc += g_pooled[b * DMODEL + d] * pW1[d * 64 + j];
        acc = (acc - mean[j]) * (1.0f / sqrtf(var[j] + 1e-12f)) * gamma[j] + beta[j];
        hsm[b][j] = fmaxf(acc, 0.f);
    }
    __syncthreads();
    if (t < BATCH * NHEAD) {
        const int b = t >> 4;
        const int o = t & 15;
        float acc = pb2[o];
        for (int j = 0; j < 64; j++) acc += hsm[b][j] * pW2[j * NHEAD + o];
        g_gate[b * NHEAD + o] = (acc >= 0.f) ? 1.f : 0.f;
    }
}

// ---------------- flash attention (fp32), 128 q-rows x 64 k-cols per block --
// 128 threads; microtile 8x8. tx=tid&7 -> k-col/out-dim group of 8;
// ty=tid>>3 -> q-row group of 8 (16 groups * 8 = 128 rows).
// K tile is XOR-swizzled on 16B chunks: chunk' = chunk ^ ((row>>3)&7), which
// makes the 8-lane phase loads (rows tx*8+j) conflict-free.
// Row stride 64 floats (no pad): Q/P reads are broadcast, V/P col accesses <=2-way.
#define AT_THREADS 128
#define QTILE 128
#define KTILE 64
#define QS_OFF 0
#define KS_OFF (QTILE*64)                 // 8192
#define VS_OFF (KS_OFF + KTILE*64)        // 12288
#define PS_OFF (VS_OFF + KTILE*64)        // 16384
#define MS_OFF (PS_OFF + QTILE*64)        // 24576
#define ASMEM_FLOATS (MS_OFF + KTILE)     // 24640 floats = 98560 B

__global__ __launch_bounds__(AT_THREADS, 2)
void attn_kernel(const float* __restrict__ mask, float* __restrict__ out) {
    extern __shared__ float sm[];
    float* Qs = sm + QS_OFF;
    float* Ks = sm + KS_OFF;
    float* Vs = sm + VS_OFF;
    float* Ps = sm + PS_OFF;
    float* Ms = sm + MS_OFF;

    const int bh = blockIdx.x;
    const int b = bh >> 4;
    const int h = bh & 15;
    const int q0 = blockIdx.y * QTILE;
    const int tid = threadIdx.x;
    const int tx = tid & 7;       // k-col / out-dim group
    const int ty = tid >> 3;      // q-row group (0..15)
    const int qr = ty * 8;
    const int kc0 = tx * 8;
    const int oc = tx * 8;
    const float scale = 0.125f;   // 1/sqrt(64)
    const float gate = g_gate[b * NHEAD + h];

    // load Q tile: 128 rows x 64 dims, plain layout (read as broadcast later)
    {
        const float* qg = g_q + ((size_t)(b * SEQ + q0)) * DMODEL + h * HDIM;
        for (int i = tid; i < QTILE * 16; i += AT_THREADS) {
            const int r = i >> 4;
            const int c4 = (i & 15) * 4;
            *(float4*)&Qs[r * 64 + c4] = *(const float4*)&qg[(size_t)r * DMODEL + c4];
        }
    }

    float m[8], l[8];
    float4 acc0[8], acc1[8];
#pragma unroll
    for (int i = 0; i < 8; i++) {
        m[i] = -CUDART_INF_F;
        l[i] = 0.f;
        acc0[i] = make_float4(0.f, 0.f, 0.f, 0.f);
        acc1[i] = make_float4(0.f, 0.f, 0.f, 0.f);
    }

    for (int kt = 0; kt < SEQ / KTILE; kt++) {
        __syncthreads();  // guard prior-iter reads of Ks/Vs/Ps
        {
            const float* kg = g_k + ((size_t)(b * SEQ + kt * KTILE)) * DMODEL + h * HDIM;
            const float* vg = g_v + ((size_t)(b * SEQ + kt * KTILE)) * DMODEL + h * HDIM;
            for (int i = tid; i < KTILE * 16; i += AT_THREADS) {
                const int r = i >> 4;
                const int c4 = i & 15;                    // 16B chunk index
                const int c4sw = c4 ^ ((r >> 3) & 7);     // K swizzle
                *(float4*)&Ks[r * 64 + c4sw * 4] = *(const float4*)&kg[(size_t)r * DMODEL + c4 * 4];
                *(float4*)&Vs[r * 64 + c4 * 4]   = *(const float4*)&vg[(size_t)r * DMODEL + c4 * 4];
            }
            if (tid < KTILE) Ms[tid] = mask[b * SEQ + kt * KTILE + tid];
        }
        __syncthreads();

        // scores microtile s[8][8]; K rows kc0..kc0+7 all have (row>>3)&7 == tx
        float s[8][8];
#pragma unroll
        for (int i = 0; i < 8; i++)
#pragma unroll
            for (int j = 0; j < 8; j++) s[i][j] = 0.f;

#pragma unroll
        for (int d4 = 0; d4 < 16; d4++) {
            const int ksw = (d4 ^ tx) * 4;   // swizzled chunk for this thread's K rows
            float4 qv[8], kv[8];
#pragma unroll
            for (int i = 0; i < 8; i++) qv[i] = *(float4*)&Qs[(qr + i) * 64 + d4 * 4];
#pragma unroll
            for (int j = 0; j < 8; j++) kv[j] = *(float4*)&Ks[(kc0 + j) * 64 + ksw];
#pragma unroll
            for (int i = 0; i < 8; i++)
#pragma unroll
                for (int j = 0; j < 8; j++)
                    s[i][j] += qv[i].x * kv[j].x + qv[i].y * kv[j].y +
                               qv[i].z * kv[j].z + qv[i].w * kv[j].w;
        }

        // online softmax per q-row; 8 lanes (tx 0..7, aligned subgroup) share a row
#pragma unroll
        for (int i = 0; i < 8; i++) {
            float mx = -CUDART_INF_F;
#pragma unroll
            for (int j = 0; j < 8; j++) {
                s[i][j] = s[i][j] * scale + Ms[kc0 + j];
                mx = fmaxf(mx, s[i][j]);
            }
#pragma unroll
            for (int o = 4; o >= 1; o >>= 1)
                mx = fmaxf(mx, __shfl_xor_sync(0xffffffffu, mx, o));
            const float mn = fmaxf(m[i], mx);
            const float corr = __expf(m[i] - mn);
            float ps = 0.f;
#pragma unroll
            for (int j = 0; j < 8; j++) {
                const float e = __expf(s[i][j] - mn);
                s[i][j] = e;
                ps += e;
            }
#pragma unroll
            for (int o = 4; o >= 1; o >>= 1)
                ps += __shfl_xor_sync(0xffffffffu, ps, o);
            l[i] = l[i] * corr + ps;
            m[i] = mn;
            acc0[i].x *= corr; acc0[i].y *= corr; acc0[i].z *= corr; acc0[i].w *= corr;
            acc1[i].x *= corr; acc1[i].y *= corr; acc1[i].z *= corr; acc1[i].w *= corr;
            *(float4*)&Ps[(qr + i) * 64 + kc0]     = make_float4(s[i][0], s[i][1], s[i][2], s[i][3]);
            *(float4*)&Ps[(qr + i) * 64 + kc0 + 4] = make_float4(s[i][4], s[i][5], s[i][6], s[i][7]);
        }
        __syncthreads();

        // PV: out-dims oc..oc+7, 8 q-rows; k unrolled by 4 (P read as float4, broadcast)
#pragma unroll 4
        for (int k4 = 0; k4 < KTILE / 4; k4++) {
            float4 pv[8];
#pragma unroll
            for (int i = 0; i < 8; i++) pv[i] = *(float4*)&Ps[(qr + i) * 64 + k4 * 4];
#pragma unroll
            for (int kk = 0; kk < 4; kk++) {
                const float4 v0 = *(float4*)&Vs[(k4 * 4 + kk) * 64 + oc];
                const float4 v1 = *(float4*)&Vs[(k4 * 4 + kk) * 64 + oc + 4];
#pragma unroll
                for (int i = 0; i < 8; i++) {
                    const float p = (kk == 0) ? pv[i].x : (kk == 1) ? pv[i].y
                                  : (kk == 2) ? pv[i].z : pv[i].w;
                    acc0[i].x += p * v0.x; acc0[i].y += p * v0.y;
                    acc0[i].z += p * v0.z; acc0[i].w += p * v0.w;
                    acc1[i].x += p * v1.x; acc1[i].y += p * v1.y;
                    acc1[i].z += p * v1.z; acc1[i].w += p * v1.w;
                }
            }
        }
    }

    // epilogue: normalize + gate, write [b, q, h*64 + d]
    float* og = out + ((size_t)(b * SEQ + q0)) * DMODEL + h * HDIM;
#pragma unroll
    for (int i = 0; i < 8; i++) {
        const float inv = gate / l[i];
        float4 o0 = acc0[i], o1 = acc1[i];
        o0.x *= inv; o0.y *= inv; o0.z *= inv; o0.w *= inv;
        o1.x *= inv; o1.y *= inv; o1.z *= inv; o1.w *= inv;
        *(float4*)&og[(size_t)(qr + i) * DMODEL + oc]     = o0;
        *(float4*)&og[(size_t)(qr + i) * DMODEL + oc + 4] = o1;
    }
}

// ---------------- launch ----------------
extern "C" void kernel_launch(void* const* d_in, const int* in_sizes, int n_in,
                              void* d_out, int out_size) {
    const float* X     = (const float*)d_in[0];
    const float* mask  = (const float*)d_in[1];
    const float* Wq    = (const float*)d_in[2];
    const float* bq    = (const float*)d_in[3];
    const float* Wk    = (const float*)d_in[4];
    const float* bk    = (const float*)d_in[5];
    const float* Wv    = (const float*)d_in[6];
    const float* bv    = (const float*)d_in[7];
    const float* pW1   = (const float*)d_in[8];
    const float* pb1   = (const float*)d_in[9];
    const float* gamma = (const float*)d_in[10];
    const float* beta  = (const float*)d_in[11];
    const float* mean  = (const float*)d_in[12];
    const float* var   = (const float*)d_in[13];
    const float* pW2   = (const float*)d_in[14];
    const float* pb2   = (const float*)d_in[15];
    float* out = (float*)d_out;

    dim3 gg(DMODEL / 128, MROWS / 128, 3);
    qkv_gemm<<<gg, 256>>>(X, Wq, bq, Wk, bk, Wv, bv);

    pool_kernel<<<(BATCH * DMODEL + 255) / 256, 256>>>(X);
    gate_kernel<<<1, 128>>>(pW1, pb1, gamma, beta, mean, var, pW2, pb2);

    const int smem = ASMEM_FLOATS * (int)sizeof(float);
    cudaFuncSetAttribute(attn_kernel, cudaFuncAttributeMaxDynamicSharedMemorySize, smem);
    attn_kernel<<<dim3(BATCH * NHEAD, SEQ / QTILE), AT_THREADS, smem>>>(mask, out);
}